// round 1
// baseline (speedup 1.0000x reference)
#include <cuda_runtime.h>
#include <math.h>

#define S_LEN   1024
#define D_MODEL 2048
#define NH      32
#define NKV     8
#define HD      64
#define BATCH   4
#define NTOK    (BATCH * S_LEN)      // 4096
#define KV_D    (NKV * HD)           // 512

// Scratch: __device__ globals (allocation-free per harness rules)
__device__ float g_q[NTOK * D_MODEL];     // 32 MB
__device__ float g_k[NTOK * KV_D];        //  8 MB
__device__ float g_v[NTOK * KV_D];        //  8 MB
__device__ float g_attn[NTOK * D_MODEL];  // 32 MB

// ---------------------------------------------------------------------------
// SGEMM: C[M,N] = A[M,K] @ B[K,N], all row-major fp32.
// 128x128 tile, BK=16, 256 threads, 8x8 per-thread accumulators.
// Requires M%128==0, N%128==0, K%16==0 (true for all our shapes).
// ---------------------------------------------------------------------------
__global__ __launch_bounds__(256) void sgemm128(
    const float* __restrict__ A, const float* __restrict__ B,
    float* __restrict__ C, int M, int N, int K)
{
    __shared__ float As[16][128];   // transposed: As[k][m]
    __shared__ float Bs[16][128];   // Bs[k][n]

    const int t  = threadIdx.x;
    const int tx = t & 15;          // 0..15 -> n direction
    const int ty = t >> 4;          // 0..15 -> m direction
    const int m0 = blockIdx.y * 128;
    const int n0 = blockIdx.x * 128;

    float acc[8][8];
#pragma unroll
    for (int i = 0; i < 8; i++)
#pragma unroll
        for (int j = 0; j < 8; j++) acc[i][j] = 0.0f;

    for (int k0 = 0; k0 < K; k0 += 16) {
        // Load A tile 128x16 (transposed into As)
#pragma unroll
        for (int i = 0; i < 2; i++) {
            int idx = t + i * 256;              // 0..511
            int row = idx >> 2;                 // 0..127
            int c   = (idx & 3) << 2;           // 0,4,8,12
            float4 v = *(const float4*)&A[(size_t)(m0 + row) * K + k0 + c];
            As[c + 0][row] = v.x;
            As[c + 1][row] = v.y;
            As[c + 2][row] = v.z;
            As[c + 3][row] = v.w;
        }
        // Load B tile 16x128
#pragma unroll
        for (int i = 0; i < 2; i++) {
            int idx = t + i * 256;
            int row = idx >> 5;                 // 0..15
            int c   = (idx & 31) << 2;          // 0..124
            *(float4*)&Bs[row][c] =
                *(const float4*)&B[(size_t)(k0 + row) * N + n0 + c];
        }
        __syncthreads();

#pragma unroll
        for (int kk = 0; kk < 16; kk++) {
            float4 a0 = *(float4*)&As[kk][ty * 4];
            float4 a1 = *(float4*)&As[kk][64 + ty * 4];
            float4 b0 = *(float4*)&Bs[kk][tx * 4];
            float4 b1 = *(float4*)&Bs[kk][64 + tx * 4];
            float a[8] = {a0.x, a0.y, a0.z, a0.w, a1.x, a1.y, a1.z, a1.w};
            float b[8] = {b0.x, b0.y, b0.z, b0.w, b1.x, b1.y, b1.z, b1.w};
#pragma unroll
            for (int i = 0; i < 8; i++)
#pragma unroll
                for (int j = 0; j < 8; j++)
                    acc[i][j] = fmaf(a[i], b[j], acc[i][j]);
        }
        __syncthreads();
    }

    // Store C: 2x2 blocks of 4x4 float4 regions
#pragma unroll
    for (int i = 0; i < 8; i++) {
        int row = m0 + ((i < 4) ? (ty * 4 + i) : (64 + ty * 4 + i - 4));
        float4 c0 = make_float4(acc[i][0], acc[i][1], acc[i][2], acc[i][3]);
        float4 c1 = make_float4(acc[i][4], acc[i][5], acc[i][6], acc[i][7]);
        *(float4*)&C[(size_t)row * N + n0 + tx * 4]      = c0;
        *(float4*)&C[(size_t)row * N + n0 + 64 + tx * 4] = c1;
    }
}

// ---------------------------------------------------------------------------
// RoPE (interleaved even/odd pairs), in-place on [NTOK, nheads*HD]
// ---------------------------------------------------------------------------
__global__ void rope_kernel(float* __restrict__ buf,
                            const float* __restrict__ cosb,
                            const float* __restrict__ sinb,
                            int nheads)
{
    int id = blockIdx.x * blockDim.x + threadIdx.x;
    int total = NTOK * nheads * (HD / 2);
    if (id >= total) return;
    int pair = id & 31;                   // HD/2 = 32
    int head = (id >> 5) % nheads;
    int tok  = id / (nheads * 32);
    int pos  = tok & (S_LEN - 1);
    float c = cosb[pos * 32 + pair];
    float s = sinb[pos * 32 + pair];
    float* p = buf + (size_t)tok * nheads * HD + head * HD + 2 * pair;
    float e = p[0], o = p[1];
    p[0] = e * c - o * s;
    p[1] = e * s + o * c;
}

// ---------------------------------------------------------------------------
// Causal flash attention with GQA.
// One block per (q_tile, batch*head). 64 q-rows x 64 k-cols x 64 dims tiles.
// blockDim = 256 laid out as 16x16; each thread owns a 4x4 micro-tile.
// ---------------------------------------------------------------------------
__global__ __launch_bounds__(256) void attn_kernel()
{
    __shared__ float Qs[64 * 64];    // Qs[row][d]
    __shared__ float KPs[64 * 64];   // phase 1: K^T[d][keycol]; phase 2: P[row][keycol]
    __shared__ float Vs[64 * 64];    // Vs[keyrow][d]

    const int qt  = blockIdx.x;         // 0..15
    const int bh  = blockIdx.y;         // 0..127
    const int b   = bh >> 5;
    const int h   = bh & 31;
    const int kvh = h >> 2;             // GQA: 4 q-heads per kv-head
    const int t   = threadIdx.x;
    const int tx  = t & 15;
    const int ty  = t >> 4;
    const int qtok0 = b * S_LEN + qt * 64;

    // Load Q tile (64x64)
#pragma unroll
    for (int i = 0; i < 4; i++) {
        int idx = t + i * 256;              // 0..1023 float4s
        int r   = idx >> 4;
        int c4  = (idx & 15) << 2;
        *(float4*)&Qs[r * 64 + c4] =
            *(const float4*)&g_q[(size_t)(qtok0 + r) * D_MODEL + h * HD + c4];
    }

    float m[4], l[4], acc[4][4];
#pragma unroll
    for (int i = 0; i < 4; i++) {
        m[i] = -INFINITY; l[i] = 0.0f;
#pragma unroll
        for (int j = 0; j < 4; j++) acc[i][j] = 0.0f;
    }

    for (int kt = 0; kt <= qt; kt++) {
        const int ktok0 = b * S_LEN + kt * 64;
        // Load K (transposed into KPs) and V
#pragma unroll
        for (int i = 0; i < 4; i++) {
            int idx = t + i * 256;
            int r   = idx >> 4;
            int c4  = (idx & 15) << 2;
            float4 kv = *(const float4*)&g_k[(size_t)(ktok0 + r) * KV_D + kvh * HD + c4];
            KPs[(c4 + 0) * 64 + r] = kv.x;
            KPs[(c4 + 1) * 64 + r] = kv.y;
            KPs[(c4 + 2) * 64 + r] = kv.z;
            KPs[(c4 + 3) * 64 + r] = kv.w;
            *(float4*)&Vs[r * 64 + c4] =
                *(const float4*)&g_v[(size_t)(ktok0 + r) * KV_D + kvh * HD + c4];
        }
        __syncthreads();

        // Scores: s[i][j] = sum_d Q[4ty+i][d] * K[4tx+j][d]
        float s[4][4];
#pragma unroll
        for (int i = 0; i < 4; i++)
#pragma unroll
            for (int j = 0; j < 4; j++) s[i][j] = 0.0f;

        for (int k = 0; k < 64; k += 4) {
            float4 av[4];
#pragma unroll
            for (int i = 0; i < 4; i++)
                av[i] = *(float4*)&Qs[(4 * ty + i) * 64 + k];
#pragma unroll
            for (int kk = 0; kk < 4; kk++) {
                float4 bv = *(float4*)&KPs[(k + kk) * 64 + 4 * tx];
#pragma unroll
                for (int i = 0; i < 4; i++) {
                    float aa = (kk == 0) ? av[i].x : (kk == 1) ? av[i].y
                             : (kk == 2) ? av[i].z : av[i].w;
                    s[i][0] = fmaf(aa, bv.x, s[i][0]);
                    s[i][1] = fmaf(aa, bv.y, s[i][1]);
                    s[i][2] = fmaf(aa, bv.z, s[i][2]);
                    s[i][3] = fmaf(aa, bv.w, s[i][3]);
                }
            }
        }

        const float sc = 0.125f;   // 1/sqrt(64)
#pragma unroll
        for (int i = 0; i < 4; i++)
#pragma unroll
            for (int j = 0; j < 4; j++) s[i][j] *= sc;

        if (kt == qt) {
#pragma unroll
            for (int i = 0; i < 4; i++)
#pragma unroll
                for (int j = 0; j < 4; j++)
                    if (4 * tx + j > 4 * ty + i) s[i][j] = -INFINITY;
        }

        // Online softmax update (row reductions over 16 lanes via shfl.xor)
#pragma unroll
        for (int i = 0; i < 4; i++) {
            float tm = fmaxf(fmaxf(s[i][0], s[i][1]), fmaxf(s[i][2], s[i][3]));
#pragma unroll
            for (int off = 8; off >= 1; off >>= 1)
                tm = fmaxf(tm, __shfl_xor_sync(0xffffffffu, tm, off));
            float nm   = fmaxf(m[i], tm);
            float corr = expf(m[i] - nm);
            float rs = 0.0f;
#pragma unroll
            for (int j = 0; j < 4; j++) {
                s[i][j] = expf(s[i][j] - nm);
                rs += s[i][j];
            }
#pragma unroll
            for (int off = 8; off >= 1; off >>= 1)
                rs += __shfl_xor_sync(0xffffffffu, rs, off);
            l[i] = l[i] * corr + rs;
            m[i] = nm;
#pragma unroll
            for (int j = 0; j < 4; j++) acc[i][j] *= corr;
        }
        __syncthreads();   // everyone done reading K^T from KPs

        // Write P into KPs (reuse buffer)
#pragma unroll
        for (int i = 0; i < 4; i++)
#pragma unroll
            for (int j = 0; j < 4; j++)
                KPs[(4 * ty + i) * 64 + 4 * tx + j] = s[i][j];
        __syncthreads();

        // acc += P @ V
        for (int j = 0; j < 64; j++) {
            float4 v4 = *(float4*)&Vs[j * 64 + 4 * tx];
            float pv[4];
#pragma unroll
            for (int i = 0; i < 4; i++) pv[i] = KPs[(4 * ty + i) * 64 + j];
#pragma unroll
            for (int i = 0; i < 4; i++) {
                acc[i][0] = fmaf(pv[i], v4.x, acc[i][0]);
                acc[i][1] = fmaf(pv[i], v4.y, acc[i][1]);
                acc[i][2] = fmaf(pv[i], v4.z, acc[i][2]);
                acc[i][3] = fmaf(pv[i], v4.w, acc[i][3]);
            }
        }
        __syncthreads();   // before next tile overwrites KPs/Vs
    }

    // Normalize and write O to g_attn[(token), h*64+d]
#pragma unroll
    for (int i = 0; i < 4; i++) {
        float inv = 1.0f / l[i];
        float4 o = make_float4(acc[i][0] * inv, acc[i][1] * inv,
                               acc[i][2] * inv, acc[i][3] * inv);
        *(float4*)&g_attn[(size_t)(qtok0 + 4 * ty + i) * D_MODEL + h * HD + 4 * tx] = o;
    }
}

// ---------------------------------------------------------------------------
// Launch
// ---------------------------------------------------------------------------
extern "C" void kernel_launch(void* const* d_in, const int* in_sizes, int n_in,
                              void* d_out, int out_size)
{
    const float* x    = (const float*)d_in[0];
    const float* cosb = (const float*)d_in[1];
    const float* sinb = (const float*)d_in[2];
    const float* wq   = (const float*)d_in[3];
    const float* wk   = (const float*)d_in[4];
    const float* wv   = (const float*)d_in[5];
    const float* wo   = (const float*)d_in[6];
    float* out = (float*)d_out;

    float *q, *k, *v, *ao;
    cudaGetSymbolAddress((void**)&q,  g_q);
    cudaGetSymbolAddress((void**)&k,  g_k);
    cudaGetSymbolAddress((void**)&v,  g_v);
    cudaGetSymbolAddress((void**)&ao, g_attn);

    // QKV projections
    sgemm128<<<dim3(D_MODEL / 128, NTOK / 128), 256>>>(x, wq, q, NTOK, D_MODEL, D_MODEL);
    sgemm128<<<dim3(KV_D   / 128, NTOK / 128), 256>>>(x, wk, k, NTOK, KV_D,   D_MODEL);
    sgemm128<<<dim3(KV_D   / 128, NTOK / 128), 256>>>(x, wv, v, NTOK, KV_D,   D_MODEL);

    // RoPE on Q and K
    {
        int totq = NTOK * NH  * (HD / 2);
        int totk = NTOK * NKV * (HD / 2);
        rope_kernel<<<(totq + 255) / 256, 256>>>(q, cosb, sinb, NH);
        rope_kernel<<<(totk + 255) / 256, 256>>>(k, cosb, sinb, NKV);
    }

    // Attention
    attn_kernel<<<dim3(S_LEN / 64, BATCH * NH), 256>>>();

    // Output projection
    sgemm128<<<dim3(D_MODEL / 128, NTOK / 128), 256>>>(ao, wo, out, NTOK, D_MODEL, D_MODEL);
}

// round 3
// speedup vs baseline: 1.8311x; 1.8311x over previous
#include <cuda_runtime.h>
#include <cuda_bf16.h>
#include <math.h>
#include <stdint.h>

#define S_LEN   1024
#define D_MODEL 2048
#define NH      32
#define NKV     8
#define HD      64
#define BATCH   4
#define NTOK    (BATCH * S_LEN)      // 4096
#define KV_D    (NKV * HD)           // 512

// ---------------------------------------------------------------------------
// Scratch (__device__ globals; allocation-free per harness rules)
// ---------------------------------------------------------------------------
__device__ float g_q[NTOK * D_MODEL];
__device__ float g_k[NTOK * KV_D];
__device__ float g_v[NTOK * KV_D];
__device__ __nv_bfloat16 g_xh[NTOK * D_MODEL],     g_xl[NTOK * D_MODEL];
__device__ __nv_bfloat16 g_wqh[D_MODEL * D_MODEL], g_wql[D_MODEL * D_MODEL];
__device__ __nv_bfloat16 g_wkh[KV_D * D_MODEL],    g_wkl[KV_D * D_MODEL];
__device__ __nv_bfloat16 g_wvh[KV_D * D_MODEL],    g_wvl[KV_D * D_MODEL];
__device__ __nv_bfloat16 g_woh[D_MODEL * D_MODEL], g_wol[D_MODEL * D_MODEL];
__device__ __nv_bfloat16 g_aoh[NTOK * D_MODEL],    g_aol[NTOK * D_MODEL];

// ---------------------------------------------------------------------------
// Warp-MMA helpers (sm_80+ features only — no 'a'-suffix instructions)
// ---------------------------------------------------------------------------
__device__ __forceinline__ uint32_t smem_u32(const void* p) {
    uint32_t a;
    asm("{ .reg .u64 t; cvta.to.shared.u64 t, %1; cvt.u32.u64 %0, t; }"
        : "=r"(a) : "l"(p));
    return a;
}
__device__ __forceinline__ void ldsm4(uint32_t* r, uint32_t addr) {
    asm volatile("ldmatrix.sync.aligned.m8n8.x4.shared.b16 {%0,%1,%2,%3}, [%4];"
        : "=r"(r[0]), "=r"(r[1]), "=r"(r[2]), "=r"(r[3]) : "r"(addr));
}
__device__ __forceinline__ void mma16816(float* d, const uint32_t* a, const uint32_t* b) {
    asm volatile("mma.sync.aligned.m16n8k16.row.col.f32.bf16.bf16.f32 "
        "{%0,%1,%2,%3}, {%4,%5,%6,%7}, {%8,%9}, {%0,%1,%2,%3};"
        : "+f"(d[0]), "+f"(d[1]), "+f"(d[2]), "+f"(d[3])
        : "r"(a[0]), "r"(a[1]), "r"(a[2]), "r"(a[3]), "r"(b[0]), "r"(b[1]));
}
#define CP_ASYNC16(saddr, gaddr) \
    asm volatile("cp.async.cg.shared.global [%0], [%1], 16;" :: "r"(saddr), "l"(gaddr))
#define CP_COMMIT()  asm volatile("cp.async.commit_group;" ::: "memory")
#define CP_WAIT(n)   asm volatile("cp.async.wait_group %0;" :: "n"(n) : "memory")

// ---------------------------------------------------------------------------
// Prep kernels: fp32 -> bf16 hi/lo split (and weight transpose to [N,K])
// ---------------------------------------------------------------------------
__global__ void split_bf16(const float* __restrict__ in,
                           __nv_bfloat16* __restrict__ hi,
                           __nv_bfloat16* __restrict__ lo, int n)
{
    int i = (blockIdx.x * blockDim.x + threadIdx.x) * 4;
    if (i >= n) return;
    float4 v = *(const float4*)(in + i);
    float a[4] = {v.x, v.y, v.z, v.w};
    __nv_bfloat162 H0, H1, L0, L1;
    __nv_bfloat16 h0 = __float2bfloat16(a[0]), h1 = __float2bfloat16(a[1]);
    __nv_bfloat16 h2 = __float2bfloat16(a[2]), h3 = __float2bfloat16(a[3]);
    H0.x = h0; H0.y = h1; H1.x = h2; H1.y = h3;
    L0.x = __float2bfloat16(a[0] - __bfloat162float(h0));
    L0.y = __float2bfloat16(a[1] - __bfloat162float(h1));
    L1.x = __float2bfloat16(a[2] - __bfloat162float(h2));
    L1.y = __float2bfloat16(a[3] - __bfloat162float(h3));
    *(__nv_bfloat162*)(hi + i)     = H0;
    *(__nv_bfloat162*)(hi + i + 2) = H1;
    *(__nv_bfloat162*)(lo + i)     = L0;
    *(__nv_bfloat162*)(lo + i + 2) = L1;
}

// W[K,N] fp32 -> Wt_hi/Wt_lo[N,K] bf16
__global__ void transpose_split(const float* __restrict__ W,
                                __nv_bfloat16* __restrict__ Th,
                                __nv_bfloat16* __restrict__ Tl, int K, int N)
{
    __shared__ float t[32][33];
    int n0 = blockIdx.x * 32, k0 = blockIdx.y * 32;
    int x = threadIdx.x, y = threadIdx.y;
#pragma unroll
    for (int i = 0; i < 32; i += 8)
        t[y + i][x] = W[(size_t)(k0 + y + i) * N + n0 + x];
    __syncthreads();
#pragma unroll
    for (int i = 0; i < 32; i += 8) {
        float v = t[x][y + i];
        __nv_bfloat16 h  = __float2bfloat16(v);
        __nv_bfloat16 lo = __float2bfloat16(v - __bfloat162float(h));
        size_t o = (size_t)(n0 + y + i) * K + k0 + x;
        Th[o] = h; Tl[o] = lo;
    }
}

// ---------------------------------------------------------------------------
// bf16x3 warp-MMA GEMM: C[M,N] f32 = (Ah+Al)[M,K] @ (Bh+Bl)[N,K]^T
// CTA 128x128, BK=32, 8 warps (each 64x32), cp.async 2-stage pipeline.
// SMEM rows padded to 40 bf16 (80 B stride) -> conflict-free ldmatrix.
// ---------------------------------------------------------------------------
#define KPAD       40
#define TILE_B     (128 * KPAD * 2)          // 10240 B per operand tile
#define STAGE_B    (4 * TILE_B)              // 40960 B per stage
#define GEMM_SMEM  (2 * STAGE_B)             // 81920 B

__global__ __launch_bounds__(256)
void gemm_bf16x3(const __nv_bfloat16* __restrict__ Ah,
                 const __nv_bfloat16* __restrict__ Al,
                 const __nv_bfloat16* __restrict__ Bh,
                 const __nv_bfloat16* __restrict__ Bl,
                 float* __restrict__ C, int M, int N, int K)
{
    extern __shared__ char smem[];
    const uint32_t sbase = smem_u32(smem);

    const int tid  = threadIdx.x;
    const int wid  = tid >> 5;
    const int lane = tid & 31;
    const int wm   = wid >> 2;          // 0..1 -> m offset 64*wm
    const int wn   = wid & 3;           // 0..3 -> n offset 32*wn
    const int m0 = blockIdx.y * 128, n0 = blockIdx.x * 128;

    const __nv_bfloat16* gsrc[4] = {
        Ah + (size_t)m0 * K, Al + (size_t)m0 * K,
        Bh + (size_t)n0 * K, Bl + (size_t)n0 * K };

    // per-thread cp.async chunk descriptors: 8 chunks of 16B per stage
    // idx = tid + i*256 in [0,2048): tile=idx>>9, c=idx&511, row=c>>2, col16=c&3
    float acc[4][4][4];
#pragma unroll
    for (int i = 0; i < 4; i++)
#pragma unroll
        for (int j = 0; j < 4; j++)
#pragma unroll
            for (int r = 0; r < 4; r++) acc[i][j][r] = 0.0f;

    const int TILES = K >> 5;

    // ldmatrix base addresses (kk=0), per warp
    // A: block i -> rows wm*64+i*16+(lane&15), col (lane>>4)*8
    uint32_t aRow = wm * 64 + (lane & 15);
    uint32_t aCol = (lane >> 4) * 8;
    // B: x4 over n16: q=lane>>3: nrow = wn*32 + j*16 + (q>>1)*8 + (lane&7), col (q&1)*8
    uint32_t q    = lane >> 3;
    uint32_t bRow = wn * 32 + (q >> 1) * 8 + (lane & 7);
    uint32_t bCol = (q & 1) * 8;

    auto load_stage = [&](int t, int s) {
        const int k0 = t << 5;
        const uint32_t sb = sbase + s * STAGE_B;
#pragma unroll
        for (int i = 0; i < 8; i++) {
            int idx  = tid + (i << 8);
            int tile = idx >> 9;
            int c    = idx & 511;
            int row  = c >> 2;
            int c16  = c & 3;
            const __nv_bfloat16* g = gsrc[tile] + (size_t)row * K + k0 + c16 * 8;
            uint32_t sa = sb + tile * TILE_B + row * (KPAD * 2) + c16 * 16;
            CP_ASYNC16(sa, g);
        }
        CP_COMMIT();
    };

    load_stage(0, 0);

    for (int t = 0; t < TILES; t++) {
        if (t + 1 < TILES) { load_stage(t + 1, (t + 1) & 1); CP_WAIT(1); }
        else               { CP_WAIT(0); }
        __syncthreads();

        const uint32_t sb = sbase + (t & 1) * STAGE_B;
        const uint32_t sAh = sb, sAl = sb + TILE_B, sBh = sb + 2 * TILE_B, sBl = sb + 3 * TILE_B;

#pragma unroll
        for (int kk = 0; kk < 32; kk += 16) {
            uint32_t ah[4][4], al[4][4], bh[2][4], bl[2][4];
#pragma unroll
            for (int i = 0; i < 4; i++)
                ldsm4(ah[i], sAh + (aRow + i * 16) * (KPAD * 2) + (aCol + kk) * 2);
#pragma unroll
            for (int j = 0; j < 2; j++)
                ldsm4(bh[j], sBh + (bRow + j * 16) * (KPAD * 2) + (bCol + kk) * 2);
            // Ah*Bh
#pragma unroll
            for (int i = 0; i < 4; i++)
#pragma unroll
                for (int j = 0; j < 4; j++)
                    mma16816(acc[i][j], ah[i], &bh[j >> 1][(j & 1) * 2]);
            // Ah*Bl
#pragma unroll
            for (int j = 0; j < 2; j++)
                ldsm4(bl[j], sBl + (bRow + j * 16) * (KPAD * 2) + (bCol + kk) * 2);
#pragma unroll
            for (int i = 0; i < 4; i++)
#pragma unroll
                for (int j = 0; j < 4; j++)
                    mma16816(acc[i][j], ah[i], &bl[j >> 1][(j & 1) * 2]);
            // Al*Bh
#pragma unroll
            for (int i = 0; i < 4; i++)
                ldsm4(al[i], sAl + (aRow + i * 16) * (KPAD * 2) + (aCol + kk) * 2);
#pragma unroll
            for (int i = 0; i < 4; i++)
#pragma unroll
                for (int j = 0; j < 4; j++)
                    mma16816(acc[i][j], al[i], &bh[j >> 1][(j & 1) * 2]);
        }
        __syncthreads();
    }

    // Epilogue: lane l owns rows (l>>2, l>>2+8), cols 2*(l&3) of each 16x8 frag
    const int mBase = m0 + wm * 64;
    const int nBase = n0 + wn * 32;
#pragma unroll
    for (int i = 0; i < 4; i++) {
#pragma unroll
        for (int j = 0; j < 4; j++) {
            int r0 = mBase + i * 16 + (lane >> 2);
            int cc = nBase + j * 8 + (lane & 3) * 2;
            *(float2*)&C[(size_t)r0 * N + cc]       = make_float2(acc[i][j][0], acc[i][j][1]);
            *(float2*)&C[(size_t)(r0 + 8) * N + cc] = make_float2(acc[i][j][2], acc[i][j][3]);
        }
    }
}

// ---------------------------------------------------------------------------
// RoPE (interleaved even/odd pairs), in-place on [NTOK, nheads*HD]
// ---------------------------------------------------------------------------
__global__ void rope_kernel(float* __restrict__ buf,
                            const float* __restrict__ cosb,
                            const float* __restrict__ sinb, int nheads)
{
    int id = blockIdx.x * blockDim.x + threadIdx.x;
    int total = NTOK * nheads * (HD / 2);
    if (id >= total) return;
    int pair = id & 31;
    int head = (id >> 5) % nheads;
    int tok  = id / (nheads * 32);
    int pos  = tok & (S_LEN - 1);
    float c = cosb[pos * 32 + pair];
    float s = sinb[pos * 32 + pair];
    float* p = buf + (size_t)tok * nheads * HD + head * HD + 2 * pair;
    float e = p[0], o = p[1];
    p[0] = e * c - o * s;
    p[1] = e * s + o * c;
}

// ---------------------------------------------------------------------------
// Causal flash attention (fp32), GQA. Output written as bf16 hi/lo for O-proj.
// ---------------------------------------------------------------------------
__global__ __launch_bounds__(256) void attn_kernel()
{
    __shared__ float Qs[64 * 64];
    __shared__ float KPs[64 * 64];
    __shared__ float Vs[64 * 64];

    const int qt  = blockIdx.x;
    const int bh  = blockIdx.y;
    const int b   = bh >> 5;
    const int h   = bh & 31;
    const int kvh = h >> 2;
    const int t   = threadIdx.x;
    const int tx  = t & 15;
    const int ty  = t >> 4;
    const int qtok0 = b * S_LEN + qt * 64;

#pragma unroll
    for (int i = 0; i < 4; i++) {
        int idx = t + i * 256;
        int r   = idx >> 4;
        int c4  = (idx & 15) << 2;
        *(float4*)&Qs[r * 64 + c4] =
            *(const float4*)&g_q[(size_t)(qtok0 + r) * D_MODEL + h * HD + c4];
    }

    float m[4], l[4], acc[4][4];
#pragma unroll
    for (int i = 0; i < 4; i++) {
        m[i] = -INFINITY; l[i] = 0.0f;
#pragma unroll
        for (int j = 0; j < 4; j++) acc[i][j] = 0.0f;
    }

    for (int kt = 0; kt <= qt; kt++) {
        const int ktok0 = b * S_LEN + kt * 64;
#pragma unroll
        for (int i = 0; i < 4; i++) {
            int idx = t + i * 256;
            int r   = idx >> 4;
            int c4  = (idx & 15) << 2;
            float4 kv = *(const float4*)&g_k[(size_t)(ktok0 + r) * KV_D + kvh * HD + c4];
            KPs[(c4 + 0) * 64 + r] = kv.x;
            KPs[(c4 + 1) * 64 + r] = kv.y;
            KPs[(c4 + 2) * 64 + r] = kv.z;
            KPs[(c4 + 3) * 64 + r] = kv.w;
            *(float4*)&Vs[r * 64 + c4] =
                *(const float4*)&g_v[(size_t)(ktok0 + r) * KV_D + kvh * HD + c4];
        }
        __syncthreads();

        float s[4][4];
#pragma unroll
        for (int i = 0; i < 4; i++)
#pragma unroll
            for (int j = 0; j < 4; j++) s[i][j] = 0.0f;

        for (int k = 0; k < 64; k += 4) {
            float4 av[4];
#pragma unroll
            for (int i = 0; i < 4; i++)
                av[i] = *(float4*)&Qs[(4 * ty + i) * 64 + k];
#pragma unroll
            for (int kk = 0; kk < 4; kk++) {
                float4 bv = *(float4*)&KPs[(k + kk) * 64 + 4 * tx];
#pragma unroll
                for (int i = 0; i < 4; i++) {
                    float aa = (kk == 0) ? av[i].x : (kk == 1) ? av[i].y
                             : (kk == 2) ? av[i].z : av[i].w;
                    s[i][0] = fmaf(aa, bv.x, s[i][0]);
                    s[i][1] = fmaf(aa, bv.y, s[i][1]);
                    s[i][2] = fmaf(aa, bv.z, s[i][2]);
                    s[i][3] = fmaf(aa, bv.w, s[i][3]);
                }
            }
        }

        const float sc = 0.125f;
#pragma unroll
        for (int i = 0; i < 4; i++)
#pragma unroll
            for (int j = 0; j < 4; j++) s[i][j] *= sc;

        if (kt == qt) {
#pragma unroll
            for (int i = 0; i < 4; i++)
#pragma unroll
                for (int j = 0; j < 4; j++)
                    if (4 * tx + j > 4 * ty + i) s[i][j] = -INFINITY;
        }

#pragma unroll
        for (int i = 0; i < 4; i++) {
            float tm = fmaxf(fmaxf(s[i][0], s[i][1]), fmaxf(s[i][2], s[i][3]));
#pragma unroll
            for (int off = 8; off >= 1; off >>= 1)
                tm = fmaxf(tm, __shfl_xor_sync(0xffffffffu, tm, off));
            float nm   = fmaxf(m[i], tm);
            float corr = expf(m[i] - nm);
            float rs = 0.0f;
#pragma unroll
            for (int j = 0; j < 4; j++) {
                s[i][j] = expf(s[i][j] - nm);
                rs += s[i][j];
            }
#pragma unroll
            for (int off = 8; off >= 1; off >>= 1)
                rs += __shfl_xor_sync(0xffffffffu, rs, off);
            l[i] = l[i] * corr + rs;
            m[i] = nm;
#pragma unroll
            for (int j = 0; j < 4; j++) acc[i][j] *= corr;
        }
        __syncthreads();

#pragma unroll
        for (int i = 0; i < 4; i++)
#pragma unroll
            for (int j = 0; j < 4; j++)
                KPs[(4 * ty + i) * 64 + 4 * tx + j] = s[i][j];
        __syncthreads();

        for (int j = 0; j < 64; j++) {
            float4 v4 = *(float4*)&Vs[j * 64 + 4 * tx];
            float pv[4];
#pragma unroll
            for (int i = 0; i < 4; i++) pv[i] = KPs[(4 * ty + i) * 64 + j];
#pragma unroll
            for (int i = 0; i < 4; i++) {
                acc[i][0] = fmaf(pv[i], v4.x, acc[i][0]);
                acc[i][1] = fmaf(pv[i], v4.y, acc[i][1]);
                acc[i][2] = fmaf(pv[i], v4.z, acc[i][2]);
                acc[i][3] = fmaf(pv[i], v4.w, acc[i][3]);
            }
        }
        __syncthreads();
    }

    // Normalize; write bf16 hi/lo directly (feeds O-projection A operand)
#pragma unroll
    for (int i = 0; i < 4; i++) {
        float inv = 1.0f / l[i];
        float o0 = acc[i][0] * inv, o1 = acc[i][1] * inv;
        float o2 = acc[i][2] * inv, o3 = acc[i][3] * inv;
        __nv_bfloat16 h0 = __float2bfloat16(o0), h1 = __float2bfloat16(o1);
        __nv_bfloat16 h2 = __float2bfloat16(o2), h3 = __float2bfloat16(o3);
        __nv_bfloat162 H0, H1, L0, L1;
        H0.x = h0; H0.y = h1; H1.x = h2; H1.y = h3;
        L0.x = __float2bfloat16(o0 - __bfloat162float(h0));
        L0.y = __float2bfloat16(o1 - __bfloat162float(h1));
        L1.x = __float2bfloat16(o2 - __bfloat162float(h2));
        L1.y = __float2bfloat16(o3 - __bfloat162float(h3));
        size_t base = (size_t)(qtok0 + 4 * ty + i) * D_MODEL + h * HD + 4 * tx;
        *(__nv_bfloat162*)&g_aoh[base]     = H0;
        *(__nv_bfloat162*)&g_aoh[base + 2] = H1;
        *(__nv_bfloat162*)&g_aol[base]     = L0;
        *(__nv_bfloat162*)&g_aol[base + 2] = L1;
    }
}

// ---------------------------------------------------------------------------
// Launch
// ---------------------------------------------------------------------------
extern "C" void kernel_launch(void* const* d_in, const int* in_sizes, int n_in,
                              void* d_out, int out_size)
{
    const float* x    = (const float*)d_in[0];
    const float* cosb = (const float*)d_in[1];
    const float* sinb = (const float*)d_in[2];
    const float* wq   = (const float*)d_in[3];
    const float* wk   = (const float*)d_in[4];
    const float* wv   = (const float*)d_in[5];
    const float* wo   = (const float*)d_in[6];
    float* out = (float*)d_out;

    float *qf, *kf, *vf;
    __nv_bfloat16 *xh, *xl, *wqh, *wql, *wkh, *wkl, *wvh, *wvl, *woh, *wol, *aoh, *aol;
    cudaGetSymbolAddress((void**)&qf,  g_q);
    cudaGetSymbolAddress((void**)&kf,  g_k);
    cudaGetSymbolAddress((void**)&vf,  g_v);
    cudaGetSymbolAddress((void**)&xh,  g_xh);  cudaGetSymbolAddress((void**)&xl,  g_xl);
    cudaGetSymbolAddress((void**)&wqh, g_wqh); cudaGetSymbolAddress((void**)&wql, g_wql);
    cudaGetSymbolAddress((void**)&wkh, g_wkh); cudaGetSymbolAddress((void**)&wkl, g_wkl);
    cudaGetSymbolAddress((void**)&wvh, g_wvh); cudaGetSymbolAddress((void**)&wvl, g_wvl);
    cudaGetSymbolAddress((void**)&woh, g_woh); cudaGetSymbolAddress((void**)&wol, g_wol);
    cudaGetSymbolAddress((void**)&aoh, g_aoh); cudaGetSymbolAddress((void**)&aol, g_aol);

    cudaFuncSetAttribute(gemm_bf16x3, cudaFuncAttributeMaxDynamicSharedMemorySize, GEMM_SMEM);

    // Prep: split x, transpose+split weights
    {
        int nx = NTOK * D_MODEL;
        split_bf16<<<nx / 4 / 256, 256>>>(x, xh, xl, nx);
        transpose_split<<<dim3(D_MODEL / 32, D_MODEL / 32), dim3(32, 8)>>>(wq, wqh, wql, D_MODEL, D_MODEL);
        transpose_split<<<dim3(KV_D   / 32, D_MODEL / 32), dim3(32, 8)>>>(wk, wkh, wkl, D_MODEL, KV_D);
        transpose_split<<<dim3(KV_D   / 32, D_MODEL / 32), dim3(32, 8)>>>(wv, wvh, wvl, D_MODEL, KV_D);
        transpose_split<<<dim3(D_MODEL / 32, D_MODEL / 32), dim3(32, 8)>>>(wo, woh, wol, D_MODEL, D_MODEL);
    }

    // QKV projections (warp-MMA bf16x3)
    gemm_bf16x3<<<dim3(D_MODEL / 128, NTOK / 128), 256, GEMM_SMEM>>>(xh, xl, wqh, wql, qf, NTOK, D_MODEL, D_MODEL);
    gemm_bf16x3<<<dim3(KV_D   / 128, NTOK / 128), 256, GEMM_SMEM>>>(xh, xl, wkh, wkl, kf, NTOK, KV_D,   D_MODEL);
    gemm_bf16x3<<<dim3(KV_D   / 128, NTOK / 128), 256, GEMM_SMEM>>>(xh, xl, wvh, wvl, vf, NTOK, KV_D,   D_MODEL);

    // RoPE
    {
        int totq = NTOK * NH  * (HD / 2);
        int totk = NTOK * NKV * (HD / 2);
        rope_kernel<<<(totq + 255) / 256, 256>>>(qf, cosb, sinb, NH);
        rope_kernel<<<(totk + 255) / 256, 256>>>(kf, cosb, sinb, NKV);
    }

    // Attention (writes bf16 hi/lo output)
    attn_kernel<<<dim3(S_LEN / 64, BATCH * NH), 256>>>();

    // Output projection (warp-MMA bf16x3)
    gemm_bf16x3<<<dim3(D_MODEL / 128, NTOK / 128), 256, GEMM_SMEM>>>(aoh, aol, woh, wol, out, NTOK, D_MODEL, D_MODEL);
}

// round 5
// speedup vs baseline: 2.5597x; 1.3979x over previous
#include <cuda_runtime.h>
#include <cuda_bf16.h>
#include <math.h>
#include <stdint.h>

#define S_LEN   1024
#define D_MODEL 2048
#define NH      32
#define NKV     8
#define HD      64
#define BATCH   4
#define NTOK    (BATCH * S_LEN)      // 4096
#define KV_D    (NKV * HD)           // 512

// ---------------------------------------------------------------------------
// Scratch (__device__ globals; allocation-free per harness rules)
// ---------------------------------------------------------------------------
__device__ float g_q[NTOK * D_MODEL];
__device__ float g_k[NTOK * KV_D];
__device__ float g_v[NTOK * KV_D];
__device__ __nv_bfloat16 g_xh[NTOK * D_MODEL],     g_xl[NTOK * D_MODEL];
__device__ __nv_bfloat16 g_wqh[D_MODEL * D_MODEL], g_wql[D_MODEL * D_MODEL];
__device__ __nv_bfloat16 g_wkh[KV_D * D_MODEL],    g_wkl[KV_D * D_MODEL];
__device__ __nv_bfloat16 g_wvh[KV_D * D_MODEL],    g_wvl[KV_D * D_MODEL];
__device__ __nv_bfloat16 g_woh[D_MODEL * D_MODEL], g_wol[D_MODEL * D_MODEL];
__device__ __nv_bfloat16 g_aoh[NTOK * D_MODEL],    g_aol[NTOK * D_MODEL];
// attention operand buffers (bf16 hi/lo)
__device__ __nv_bfloat16 g_qbh[NTOK * D_MODEL],    g_qbl[NTOK * D_MODEL];
__device__ __nv_bfloat16 g_kbh[NTOK * KV_D],       g_kbl[NTOK * KV_D];
__device__ __nv_bfloat16 g_vth[NTOK * KV_D],       g_vtl[NTOK * KV_D];

// ---------------------------------------------------------------------------
// Warp-MMA helpers (sm_80+ features only)
// ---------------------------------------------------------------------------
__device__ __forceinline__ uint32_t smem_u32(const void* p) {
    uint32_t a;
    asm("{ .reg .u64 t; cvta.to.shared.u64 t, %1; cvt.u32.u64 %0, t; }"
        : "=r"(a) : "l"(p));
    return a;
}
__device__ __forceinline__ void ldsm4(uint32_t* r, uint32_t addr) {
    asm volatile("ldmatrix.sync.aligned.m8n8.x4.shared.b16 {%0,%1,%2,%3}, [%4];"
        : "=r"(r[0]), "=r"(r[1]), "=r"(r[2]), "=r"(r[3]) : "r"(addr));
}
__device__ __forceinline__ void mma16816(float* d, const uint32_t* a, const uint32_t* b) {
    asm volatile("mma.sync.aligned.m16n8k16.row.col.f32.bf16.bf16.f32 "
        "{%0,%1,%2,%3}, {%4,%5,%6,%7}, {%8,%9}, {%0,%1,%2,%3};"
        : "+f"(d[0]), "+f"(d[1]), "+f"(d[2]), "+f"(d[3])
        : "r"(a[0]), "r"(a[1]), "r"(a[2]), "r"(a[3]), "r"(b[0]), "r"(b[1]));
}
#define CP_ASYNC16(saddr, gaddr) \
    asm volatile("cp.async.cg.shared.global [%0], [%1], 16;" :: "r"(saddr), "l"(gaddr))
#define CP_COMMIT()  asm volatile("cp.async.commit_group;" ::: "memory")
#define CP_WAIT(n)   asm volatile("cp.async.wait_group %0;" :: "n"(n) : "memory")

// exp on the FMA pipe (avoids the MUFU throughput floor). x <= 0 expected.
__device__ __forceinline__ float fexp(float x) {
    x = fmaxf(x, -80.0f);
    float y = x * 1.4426950408889634f;
    float n = rintf(y);
    float f = y - n;
    float p = 0.0013333558f;
    p = fmaf(p, f, 0.0096181291f);
    p = fmaf(p, f, 0.0555041087f);
    p = fmaf(p, f, 0.2402264791f);
    p = fmaf(p, f, 0.6931471806f);
    p = fmaf(p, f, 1.0f);
    return p * __int_as_float(((int)n + 127) << 23);
}

__device__ __forceinline__ __nv_bfloat162 hi_pair(float a, float b, float2& rem) {
    __nv_bfloat162 h;
    h.x = __float2bfloat16(a); h.y = __float2bfloat16(b);
    rem.x = a - __bfloat162float(h.x);
    rem.y = b - __bfloat162float(h.y);
    return h;
}

// ---------------------------------------------------------------------------
// Prep kernels
// ---------------------------------------------------------------------------
__global__ void split_bf16(const float* __restrict__ in,
                           __nv_bfloat16* __restrict__ hi,
                           __nv_bfloat16* __restrict__ lo, int n)
{
    int i = (blockIdx.x * blockDim.x + threadIdx.x) * 4;
    if (i >= n) return;
    float4 v = *(const float4*)(in + i);
    float2 r0, r1;
    __nv_bfloat162 H0 = hi_pair(v.x, v.y, r0);
    __nv_bfloat162 H1 = hi_pair(v.z, v.w, r1);
    __nv_bfloat162 L0, L1;
    L0.x = __float2bfloat16(r0.x); L0.y = __float2bfloat16(r0.y);
    L1.x = __float2bfloat16(r1.x); L1.y = __float2bfloat16(r1.y);
    *(__nv_bfloat162*)(hi + i)     = H0;
    *(__nv_bfloat162*)(hi + i + 2) = H1;
    *(__nv_bfloat162*)(lo + i)     = L0;
    *(__nv_bfloat162*)(lo + i + 2) = L1;
}

__global__ void transpose_split(const float* __restrict__ W,
                                __nv_bfloat16* __restrict__ Th,
                                __nv_bfloat16* __restrict__ Tl, int K, int N)
{
    __shared__ float t[32][33];
    int n0 = blockIdx.x * 32, k0 = blockIdx.y * 32;
    int x = threadIdx.x, y = threadIdx.y;
#pragma unroll
    for (int i = 0; i < 32; i += 8)
        t[y + i][x] = W[(size_t)(k0 + y + i) * N + n0 + x];
    __syncthreads();
#pragma unroll
    for (int i = 0; i < 32; i += 8) {
        float v = t[x][y + i];
        __nv_bfloat16 h  = __float2bfloat16(v);
        __nv_bfloat16 lo = __float2bfloat16(v - __bfloat162float(h));
        size_t o = (size_t)(n0 + y + i) * K + k0 + x;
        Th[o] = h; Tl[o] = lo;
    }
}

// RoPE + scale + hi/lo bf16 pack (Q: scale=0.125 folds score scaling in)
__global__ void pack_rope(const float* __restrict__ src,
                          const float* __restrict__ cosb,
                          const float* __restrict__ sinb,
                          __nv_bfloat16* __restrict__ Dh,
                          __nv_bfloat16* __restrict__ Dl,
                          int nheads, float scale)
{
    int id = blockIdx.x * blockDim.x + threadIdx.x;
    int total = NTOK * nheads * (HD / 2);
    if (id >= total) return;
    int pair = id & 31;
    int head = (id >> 5) % nheads;
    int tok  = id / (nheads * 32);
    int pos  = tok & (S_LEN - 1);
    float c = cosb[pos * 32 + pair];
    float s = sinb[pos * 32 + pair];
    size_t off = (size_t)tok * nheads * HD + head * HD + 2 * pair;
    float2 eo = *(const float2*)(src + off);
    float re = (eo.x * c - eo.y * s) * scale;
    float im = (eo.x * s + eo.y * c) * scale;
    float2 rem;
    __nv_bfloat162 H = hi_pair(re, im, rem);
    __nv_bfloat162 L;
    L.x = __float2bfloat16(rem.x); L.y = __float2bfloat16(rem.y);
    *(__nv_bfloat162*)(Dh + off) = H;
    *(__nv_bfloat162*)(Dl + off) = L;
}

// V fp32 [tok][KV_D] -> V^T bf16 hi/lo [b][kvh][d][s]
__global__ void pack_vT(const float* __restrict__ V,
                        __nv_bfloat16* __restrict__ Th,
                        __nv_bfloat16* __restrict__ Tl)
{
    __shared__ float t[32][33];
    int d0 = blockIdx.x * 32, s0 = blockIdx.y * 32, b = blockIdx.z;
    int x = threadIdx.x, y = threadIdx.y;
#pragma unroll
    for (int i = 0; i < 32; i += 8)
        t[y + i][x] = V[(size_t)(b * S_LEN + s0 + y + i) * KV_D + d0 + x];
    __syncthreads();
#pragma unroll
    for (int i = 0; i < 32; i += 8) {
        float v = t[x][y + i];               // V[s0+x][d0+y+i]
        int dg  = d0 + y + i;
        int kvh = dg >> 6, dd = dg & 63;
        __nv_bfloat16 h  = __float2bfloat16(v);
        __nv_bfloat16 lo = __float2bfloat16(v - __bfloat162float(h));
        size_t o = ((size_t)(b * NKV + kvh) * HD + dd) * S_LEN + s0 + x;
        Th[o] = h; Tl[o] = lo;
    }
}

// ---------------------------------------------------------------------------
// bf16x3 warp-MMA GEMM (unchanged from R3 passing version)
// ---------------------------------------------------------------------------
#define KPAD       40
#define TILE_B     (128 * KPAD * 2)
#define STAGE_B    (4 * TILE_B)
#define GEMM_SMEM  (2 * STAGE_B)

__global__ __launch_bounds__(256)
void gemm_bf16x3(const __nv_bfloat16* __restrict__ Ah,
                 const __nv_bfloat16* __restrict__ Al,
                 const __nv_bfloat16* __restrict__ Bh,
                 const __nv_bfloat16* __restrict__ Bl,
                 float* __restrict__ C, int M, int N, int K)
{
    extern __shared__ char smem[];
    const uint32_t sbase = smem_u32(smem);
    const int tid  = threadIdx.x;
    const int wid  = tid >> 5;
    const int lane = tid & 31;
    const int wm   = wid >> 2;
    const int wn   = wid & 3;
    const int m0 = blockIdx.y * 128, n0 = blockIdx.x * 128;

    const __nv_bfloat16* gsrc[4] = {
        Ah + (size_t)m0 * K, Al + (size_t)m0 * K,
        Bh + (size_t)n0 * K, Bl + (size_t)n0 * K };

    float acc[4][4][4];
#pragma unroll
    for (int i = 0; i < 4; i++)
#pragma unroll
        for (int j = 0; j < 4; j++)
#pragma unroll
            for (int r = 0; r < 4; r++) acc[i][j][r] = 0.0f;

    const int TILES = K >> 5;
    uint32_t aRow = wm * 64 + (lane & 15);
    uint32_t aCol = (lane >> 4) * 8;
    uint32_t q    = lane >> 3;
    uint32_t bRow = wn * 32 + (q >> 1) * 8 + (lane & 7);
    uint32_t bCol = (q & 1) * 8;

    auto load_stage = [&](int t, int s) {
        const int k0 = t << 5;
        const uint32_t sb = sbase + s * STAGE_B;
#pragma unroll
        for (int i = 0; i < 8; i++) {
            int idx  = tid + (i << 8);
            int tile = idx >> 9;
            int c    = idx & 511;
            int row  = c >> 2;
            int c16  = c & 3;
            const __nv_bfloat16* g = gsrc[tile] + (size_t)row * K + k0 + c16 * 8;
            uint32_t sa = sb + tile * TILE_B + row * (KPAD * 2) + c16 * 16;
            CP_ASYNC16(sa, g);
        }
        CP_COMMIT();
    };

    load_stage(0, 0);

    for (int t = 0; t < TILES; t++) {
        if (t + 1 < TILES) { load_stage(t + 1, (t + 1) & 1); CP_WAIT(1); }
        else               { CP_WAIT(0); }
        __syncthreads();

        const uint32_t sb = sbase + (t & 1) * STAGE_B;
        const uint32_t sAh = sb, sAl = sb + TILE_B, sBh = sb + 2 * TILE_B, sBl = sb + 3 * TILE_B;

#pragma unroll
        for (int kk = 0; kk < 32; kk += 16) {
            uint32_t ah[4][4], al[4][4], bh[2][4], bl[2][4];
#pragma unroll
            for (int i = 0; i < 4; i++)
                ldsm4(ah[i], sAh + (aRow + i * 16) * (KPAD * 2) + (aCol + kk) * 2);
#pragma unroll
            for (int j = 0; j < 2; j++)
                ldsm4(bh[j], sBh + (bRow + j * 16) * (KPAD * 2) + (bCol + kk) * 2);
#pragma unroll
            for (int i = 0; i < 4; i++)
#pragma unroll
                for (int j = 0; j < 4; j++)
                    mma16816(acc[i][j], ah[i], &bh[j >> 1][(j & 1) * 2]);
#pragma unroll
            for (int j = 0; j < 2; j++)
                ldsm4(bl[j], sBl + (bRow + j * 16) * (KPAD * 2) + (bCol + kk) * 2);
#pragma unroll
            for (int i = 0; i < 4; i++)
#pragma unroll
                for (int j = 0; j < 4; j++)
                    mma16816(acc[i][j], ah[i], &bl[j >> 1][(j & 1) * 2]);
#pragma unroll
            for (int i = 0; i < 4; i++)
                ldsm4(al[i], sAl + (aRow + i * 16) * (KPAD * 2) + (aCol + kk) * 2);
#pragma unroll
            for (int i = 0; i < 4; i++)
#pragma unroll
                for (int j = 0; j < 4; j++)
                    mma16816(acc[i][j], al[i], &bh[j >> 1][(j & 1) * 2]);
        }
        __syncthreads();
    }

    const int mBase = m0 + wm * 64;
    const int nBase = n0 + wn * 32;
#pragma unroll
    for (int i = 0; i < 4; i++) {
#pragma unroll
        for (int j = 0; j < 4; j++) {
            int r0 = mBase + i * 16 + (lane >> 2);
            int cc = nBase + j * 8 + (lane & 3) * 2;
            *(float2*)&C[(size_t)r0 * N + cc]       = make_float2(acc[i][j][0], acc[i][j][1]);
            *(float2*)&C[(size_t)(r0 + 8) * N + cc] = make_float2(acc[i][j][2], acc[i][j][3]);
        }
    }
}

// ---------------------------------------------------------------------------
// Tensor-core causal flash attention, bf16x3, GQA.
// CTA: 128 q-rows (8 warps x 16 rows) x full head. KV tiles of 64.
// smem rows padded to 72 bf16 (144 B): stride % 128 == 16 -> conflict-free.
// ---------------------------------------------------------------------------
#define AROWB  144
#define A_TILE 9216                 // 64 rows * 144 B
#define A_STAGE (4 * A_TILE)        // Kh, Kl, VTh, VTl
#define ATTN_SMEM (2 * A_STAGE)     // 73728

__global__ __launch_bounds__(256, 1)
void attn_mma(const __nv_bfloat16* __restrict__ Qh, const __nv_bfloat16* __restrict__ Ql,
              const __nv_bfloat16* __restrict__ Kh, const __nv_bfloat16* __restrict__ Kl,
              const __nv_bfloat16* __restrict__ VTh, const __nv_bfloat16* __restrict__ VTl,
              __nv_bfloat16* __restrict__ Oh, __nv_bfloat16* __restrict__ Ol)
{
    extern __shared__ char sm[];
    const uint32_t sb = smem_u32(sm);
    const int tid  = threadIdx.x;
    const int wid  = tid >> 5;
    const int lane = tid & 31;
    const int qt = blockIdx.x;              // 0..7
    const int bh = blockIdx.y;              // 0..127
    const int b  = bh >> 5;
    const int h  = bh & 31;
    const int kvh = h >> 2;
    const int qtok0 = b * S_LEN + qt * 128;

    // ---- Stage Q (hi at sb, lo at sb+18432), 2048 x 16B chunks ----
#pragma unroll
    for (int i = 0; i < 8; i++) {
        int idx = tid + (i << 8);
        int ten = idx >> 10;                // 0=hi, 1=lo
        int c   = idx & 1023;
        int r   = c >> 3;
        int ch  = c & 7;
        const __nv_bfloat16* g = (ten ? Ql : Qh)
            + (size_t)(qtok0 + r) * D_MODEL + h * HD + ch * 8;
        CP_ASYNC16(sb + ten * 18432 + r * AROWB + ch * 16, g);
    }
    CP_COMMIT(); CP_WAIT(0); __syncthreads();

    uint32_t qh[4][4], ql[4][4];
    {
        uint32_t qb = sb + (wid * 16 + (lane & 15)) * AROWB + ((lane >> 4) * 8) * 2;
#pragma unroll
        for (int kf = 0; kf < 4; kf++) {
            ldsm4(qh[kf], qb + kf * 32);
            ldsm4(ql[kf], qb + 18432 + kf * 32);
        }
    }
    __syncthreads();

    float m[2] = {-1e30f, -1e30f}, l[2] = {0.0f, 0.0f};
    float o[8][4];
#pragma unroll
    for (int f = 0; f < 8; f++)
#pragma unroll
        for (int c = 0; c < 4; c++) o[f][c] = 0.0f;

    const int T = 2 * qt + 2;

    auto load_kv = [&](int kt, int s) {
        const int ktok0 = b * S_LEN + kt * 64;
        const uint32_t st = sb + s * A_STAGE;
#pragma unroll
        for (int i = 0; i < 8; i++) {
            int idx = tid + (i << 8);
            int ten = idx >> 9;             // 0..3
            int c   = idx & 511;
            int r   = c >> 3;
            int ch  = c & 7;
            const __nv_bfloat16* g;
            if (ten == 0)      g = Kh  + (size_t)(ktok0 + r) * KV_D + kvh * HD + ch * 8;
            else if (ten == 1) g = Kl  + (size_t)(ktok0 + r) * KV_D + kvh * HD + ch * 8;
            else if (ten == 2) g = VTh + ((size_t)(b * NKV + kvh) * HD + r) * S_LEN + kt * 64 + ch * 8;
            else               g = VTl + ((size_t)(b * NKV + kvh) * HD + r) * S_LEN + kt * 64 + ch * 8;
            CP_ASYNC16(st + ten * A_TILE + r * AROWB + ch * 16, g);
        }
        CP_COMMIT();
    };

    load_kv(0, 0);
    load_kv(1, 1);

    const int q3 = lane >> 3;
    const uint32_t fragRowOff = ((q3 >> 1) * 8 + (lane & 7)) * AROWB + (q3 & 1) * 16;
    const int rowg0 = qt * 128 + wid * 16 + (lane >> 2);

    for (int kt = 0; kt < T; kt++) {
        if (kt + 1 < T) CP_WAIT(1); else CP_WAIT(0);
        __syncthreads();
        const uint32_t st = sb + (kt & 1) * A_STAGE;

        // ---- scores = Q K^T (bf16x3) ----
        float s[8][4];
#pragma unroll
        for (int f = 0; f < 8; f++)
#pragma unroll
            for (int c = 0; c < 4; c++) s[f][c] = 0.0f;

#pragma unroll
        for (int kf = 0; kf < 4; kf++) {
#pragma unroll
            for (int jj = 0; jj < 4; jj++) {
                uint32_t addr = st + fragRowOff + jj * 16 * AROWB + kf * 32;
                uint32_t kh4[4], kl4[4];
                ldsm4(kh4, addr);
                ldsm4(kl4, addr + A_TILE);
                mma16816(s[jj * 2],     qh[kf], kh4);
                mma16816(s[jj * 2 + 1], qh[kf], kh4 + 2);
                mma16816(s[jj * 2],     qh[kf], kl4);
                mma16816(s[jj * 2 + 1], qh[kf], kl4 + 2);
                mma16816(s[jj * 2],     ql[kf], kh4);
                mma16816(s[jj * 2 + 1], ql[kf], kh4 + 2);
            }
        }

        // ---- causal mask ----
        if (kt * 64 + 63 > rowg0) {
#pragma unroll
            for (int f = 0; f < 8; f++)
#pragma unroll
                for (int c = 0; c < 4; c++) {
                    int col = kt * 64 + f * 8 + 2 * (lane & 3) + (c & 1);
                    int row = rowg0 + ((c >= 2) ? 8 : 0);
                    if (col > row) s[f][c] = -1e9f;
                }
        }

        // ---- online softmax ----
        float mx0 = -1e30f, mx1 = -1e30f;
#pragma unroll
        for (int f = 0; f < 8; f++) {
            mx0 = fmaxf(mx0, fmaxf(s[f][0], s[f][1]));
            mx1 = fmaxf(mx1, fmaxf(s[f][2], s[f][3]));
        }
        mx0 = fmaxf(mx0, __shfl_xor_sync(0xffffffffu, mx0, 1));
        mx0 = fmaxf(mx0, __shfl_xor_sync(0xffffffffu, mx0, 2));
        mx1 = fmaxf(mx1, __shfl_xor_sync(0xffffffffu, mx1, 1));
        mx1 = fmaxf(mx1, __shfl_xor_sync(0xffffffffu, mx1, 2));
        float mn0 = fmaxf(m[0], mx0), mn1 = fmaxf(m[1], mx1);
        float corr0 = fexp(m[0] - mn0), corr1 = fexp(m[1] - mn1);
        float sum0 = 0.0f, sum1 = 0.0f;
#pragma unroll
        for (int f = 0; f < 8; f++) {
            s[f][0] = fexp(s[f][0] - mn0);
            s[f][1] = fexp(s[f][1] - mn0);
            s[f][2] = fexp(s[f][2] - mn1);
            s[f][3] = fexp(s[f][3] - mn1);
            sum0 += s[f][0] + s[f][1];
            sum1 += s[f][2] + s[f][3];
        }
        sum0 += __shfl_xor_sync(0xffffffffu, sum0, 1);
        sum0 += __shfl_xor_sync(0xffffffffu, sum0, 2);
        sum1 += __shfl_xor_sync(0xffffffffu, sum1, 1);
        sum1 += __shfl_xor_sync(0xffffffffu, sum1, 2);
        l[0] = l[0] * corr0 + sum0; m[0] = mn0;
        l[1] = l[1] * corr1 + sum1; m[1] = mn1;
#pragma unroll
        for (int f = 0; f < 8; f++) {
            o[f][0] *= corr0; o[f][1] *= corr0;
            o[f][2] *= corr1; o[f][3] *= corr1;
        }

        // ---- pack P to bf16 hi/lo A-fragments ----
        uint32_t ph[4][4], pl[4][4];
#pragma unroll
        for (int kf = 0; kf < 4; kf++) {
            float2 r0, r1, r2, r3;
            __nv_bfloat162 a0 = hi_pair(s[2 * kf][0],     s[2 * kf][1],     r0);
            __nv_bfloat162 a1 = hi_pair(s[2 * kf][2],     s[2 * kf][3],     r1);
            __nv_bfloat162 a2 = hi_pair(s[2 * kf + 1][0], s[2 * kf + 1][1], r2);
            __nv_bfloat162 a3 = hi_pair(s[2 * kf + 1][2], s[2 * kf + 1][3], r3);
            ph[kf][0] = *(uint32_t*)&a0; ph[kf][1] = *(uint32_t*)&a1;
            ph[kf][2] = *(uint32_t*)&a2; ph[kf][3] = *(uint32_t*)&a3;
            __nv_bfloat162 b0, b1, b2, b3;
            b0.x = __float2bfloat16(r0.x); b0.y = __float2bfloat16(r0.y);
            b1.x = __float2bfloat16(r1.x); b1.y = __float2bfloat16(r1.y);
            b2.x = __float2bfloat16(r2.x); b2.y = __float2bfloat16(r2.y);
            b3.x = __float2bfloat16(r3.x); b3.y = __float2bfloat16(r3.y);
            pl[kf][0] = *(uint32_t*)&b0; pl[kf][1] = *(uint32_t*)&b1;
            pl[kf][2] = *(uint32_t*)&b2; pl[kf][3] = *(uint32_t*)&b3;
        }

        // ---- out += P V (bf16x3); VT tiles at st + 2*A_TILE ----
#pragma unroll
        for (int kf = 0; kf < 4; kf++) {
#pragma unroll
            for (int nn = 0; nn < 4; nn++) {
                uint32_t addr = st + 2 * A_TILE + fragRowOff + nn * 16 * AROWB + kf * 32;
                uint32_t vh4[4], vl4[4];
                ldsm4(vh4, addr);
                ldsm4(vl4, addr + A_TILE);
                mma16816(o[nn * 2],     ph[kf], vh4);
                mma16816(o[nn * 2 + 1], ph[kf], vh4 + 2);
                mma16816(o[nn * 2],     ph[kf], vl4);
                mma16816(o[nn * 2 + 1], ph[kf], vl4 + 2);
                mma16816(o[nn * 2],     pl[kf], vh4);
                mma16816(o[nn * 2 + 1], pl[kf], vh4 + 2);
            }
        }
        __syncthreads();
        if (kt + 2 < T) load_kv(kt + 2, kt & 1);
    }

    // ---- epilogue: normalize, write bf16 hi/lo ----
    float inv0 = 1.0f / l[0], inv1 = 1.0f / l[1];
    const int row0 = qtok0 + wid * 16 + (lane >> 2);
#pragma unroll
    for (int f = 0; f < 8; f++) {
        int colg = h * HD + f * 8 + 2 * (lane & 3);
        float2 rem;
        __nv_bfloat162 H = hi_pair(o[f][0] * inv0, o[f][1] * inv0, rem);
        __nv_bfloat162 L;
        L.x = __float2bfloat16(rem.x); L.y = __float2bfloat16(rem.y);
        *(__nv_bfloat162*)&Oh[(size_t)row0 * D_MODEL + colg] = H;
        *(__nv_bfloat162*)&Ol[(size_t)row0 * D_MODEL + colg] = L;
        H = hi_pair(o[f][2] * inv1, o[f][3] * inv1, rem);
        L.x = __float2bfloat16(rem.x); L.y = __float2bfloat16(rem.y);
        *(__nv_bfloat162*)&Oh[(size_t)(row0 + 8) * D_MODEL + colg] = H;
        *(__nv_bfloat162*)&Ol[(size_t)(row0 + 8) * D_MODEL + colg] = L;
    }
}

// ---------------------------------------------------------------------------
// Launch
// ---------------------------------------------------------------------------
extern "C" void kernel_launch(void* const* d_in, const int* in_sizes, int n_in,
                              void* d_out, int out_size)
{
    const float* x    = (const float*)d_in[0];
    const float* cosb = (const float*)d_in[1];
    const float* sinb = (const float*)d_in[2];
    const float* wq   = (const float*)d_in[3];
    const float* wk   = (const float*)d_in[4];
    const float* wv   = (const float*)d_in[5];
    const float* wo   = (const float*)d_in[6];
    float* out = (float*)d_out;

    float *qf, *kf, *vf;
    __nv_bfloat16 *xh, *xl, *wqh, *wql, *wkh, *wkl, *wvh, *wvl, *woh, *wol, *aoh, *aol;
    __nv_bfloat16 *qbh, *qbl, *kbh, *kbl, *vth, *vtl;
    cudaGetSymbolAddress((void**)&qf,  g_q);
    cudaGetSymbolAddress((void**)&kf,  g_k);
    cudaGetSymbolAddress((void**)&vf,  g_v);
    cudaGetSymbolAddress((void**)&xh,  g_xh);  cudaGetSymbolAddress((void**)&xl,  g_xl);
    cudaGetSymbolAddress((void**)&wqh, g_wqh); cudaGetSymbolAddress((void**)&wql, g_wql);
    cudaGetSymbolAddress((void**)&wkh, g_wkh); cudaGetSymbolAddress((void**)&wkl, g_wkl);
    cudaGetSymbolAddress((void**)&wvh, g_wvh); cudaGetSymbolAddress((void**)&wvl, g_wvl);
    cudaGetSymbolAddress((void**)&woh, g_woh); cudaGetSymbolAddress((void**)&wol, g_wol);
    cudaGetSymbolAddress((void**)&aoh, g_aoh); cudaGetSymbolAddress((void**)&aol, g_aol);
    cudaGetSymbolAddress((void**)&qbh, g_qbh); cudaGetSymbolAddress((void**)&qbl, g_qbl);
    cudaGetSymbolAddress((void**)&kbh, g_kbh); cudaGetSymbolAddress((void**)&kbl, g_kbl);
    cudaGetSymbolAddress((void**)&vth, g_vth); cudaGetSymbolAddress((void**)&vtl, g_vtl);

    cudaFuncSetAttribute(gemm_bf16x3, cudaFuncAttributeMaxDynamicSharedMemorySize, GEMM_SMEM);
    cudaFuncSetAttribute(attn_mma,    cudaFuncAttributeMaxDynamicSharedMemorySize, ATTN_SMEM);

    // Prep
    {
        int nx = NTOK * D_MODEL;
        split_bf16<<<nx / 4 / 256, 256>>>(x, xh, xl, nx);
        transpose_split<<<dim3(D_MODEL / 32, D_MODEL / 32), dim3(32, 8)>>>(wq, wqh, wql, D_MODEL, D_MODEL);
        transpose_split<<<dim3(KV_D   / 32, D_MODEL / 32), dim3(32, 8)>>>(wk, wkh, wkl, D_MODEL, KV_D);
        transpose_split<<<dim3(KV_D   / 32, D_MODEL / 32), dim3(32, 8)>>>(wv, wvh, wvl, D_MODEL, KV_D);
        transpose_split<<<dim3(D_MODEL / 32, D_MODEL / 32), dim3(32, 8)>>>(wo, woh, wol, D_MODEL, D_MODEL);
    }

    // QKV projections
    gemm_bf16x3<<<dim3(D_MODEL / 128, NTOK / 128), 256, GEMM_SMEM>>>(xh, xl, wqh, wql, qf, NTOK, D_MODEL, D_MODEL);
    gemm_bf16x3<<<dim3(KV_D   / 128, NTOK / 128), 256, GEMM_SMEM>>>(xh, xl, wkh, wkl, kf, NTOK, KV_D,   D_MODEL);
    gemm_bf16x3<<<dim3(KV_D   / 128, NTOK / 128), 256, GEMM_SMEM>>>(xh, xl, wvh, wvl, vf, NTOK, KV_D,   D_MODEL);

    // RoPE + pack to bf16 hi/lo (Q carries the 1/sqrt(HD) scale)
    {
        int totq = NTOK * NH  * (HD / 2);
        int totk = NTOK * NKV * (HD / 2);
        pack_rope<<<(totq + 255) / 256, 256>>>(qf, cosb, sinb, qbh, qbl, NH,  0.125f);
        pack_rope<<<(totk + 255) / 256, 256>>>(kf, cosb, sinb, kbh, kbl, NKV, 1.0f);
        pack_vT<<<dim3(KV_D / 32, S_LEN / 32, BATCH), dim3(32, 8)>>>(vf, vth, vtl);
    }

    // Tensor-core attention
    attn_mma<<<dim3(S_LEN / 128, BATCH * NH), 256, ATTN_SMEM>>>(
        qbh, qbl, kbh, kbl, vth, vtl, aoh, aol);

    // Output projection
    gemm_bf16x3<<<dim3(D_MODEL / 128, NTOK / 128), 256, GEMM_SMEM>>>(aoh, aol, woh, wol, out, NTOK, D_MODEL, D_MODEL);
}